// round 2
// baseline (speedup 1.0000x reference)
#include <cuda_runtime.h>
#include <cstdint>

// Problem constants
#define DIMM   1024
#define BATCH  4
#define SEQ    2048
#define NHEAD  16
#define HDIM   64
#define MTOK   (BATCH*SEQ)        // 8192
#define NQKV   (3*DIMM)           // 3072
#define PLANE  (BATCH*NHEAD*SEQ*HDIM)  // 8388608 floats per Q/K/V plane

// Scratch (device globals: allocation-free per harness rules)
__device__ float g_QKV[3ULL * PLANE];            // [3][B][H][S][hd]
__device__ float g_O[(size_t)MTOK * DIMM];       // [B,S,D] attention output

// ---------------------------------------------------------------------------
// GEMM 1: QKV = x @ W_qkv + b_qkv, scattered into [3][B][H][S][hd].
// Q additionally scaled by 1/8 (= 1/sqrt(64)) so attention scores need no scale.
// Tiles: 128x128 output, BK=16, 256 threads, 8x8 per-thread register tile.
// ---------------------------------------------------------------------------
__global__ __launch_bounds__(256) void gemm_qkv_kernel(
    const float* __restrict__ X,      // [8192,1024]
    const float* __restrict__ W,      // [1024,3072]
    const float* __restrict__ bias)   // [3072]
{
    __shared__ float As[16][132];     // A transposed [k][m], padded
    __shared__ float Bs[16][128];     // B [k][n]

    const int tid = threadIdx.x;
    const int tx  = tid & 15;
    const int ty  = tid >> 4;
    const int rowbase = blockIdx.y * 128;
    const int colbase = blockIdx.x * 128;

    float acc[8][8];
#pragma unroll
    for (int i = 0; i < 8; i++)
#pragma unroll
        for (int j = 0; j < 8; j++) acc[i][j] = 0.f;

    for (int k0 = 0; k0 < DIMM; k0 += 16) {
        // Load A tile 128x16 (transposed into As)
#pragma unroll
        for (int it = 0; it < 2; it++) {
            int flat = tid + it * 256;           // float4 index, 512 total
            int r  = flat >> 2;
            int c4 = (flat & 3) * 4;
            float4 v = *(const float4*)&X[(size_t)(rowbase + r) * DIMM + k0 + c4];
            As[c4 + 0][r] = v.x;
            As[c4 + 1][r] = v.y;
            As[c4 + 2][r] = v.z;
            As[c4 + 3][r] = v.w;
        }
        // Load B tile 16x128
#pragma unroll
        for (int it = 0; it < 2; it++) {
            int flat = tid + it * 256;
            int r  = flat >> 5;
            int c4 = (flat & 31) * 4;
            *(float4*)&Bs[r][c4] = *(const float4*)&W[(size_t)(k0 + r) * NQKV + colbase + c4];
        }
        __syncthreads();

#pragma unroll
        for (int k = 0; k < 16; k++) {
            float a[8], b[8];
            *(float4*)&a[0] = *(const float4*)&As[k][ty * 8];
            *(float4*)&a[4] = *(const float4*)&As[k][ty * 8 + 4];
            *(float4*)&b[0] = *(const float4*)&Bs[k][tx * 8];
            *(float4*)&b[4] = *(const float4*)&Bs[k][tx * 8 + 4];
#pragma unroll
            for (int i = 0; i < 8; i++)
#pragma unroll
                for (int j = 0; j < 8; j++)
                    acc[i][j] += a[i] * b[j];
        }
        __syncthreads();
    }

    // Epilogue: bias + scatter to [3][B][H][S][hd], Q scaled by 0.125
    float bl[8];
#pragma unroll
    for (int j = 0; j < 8; j++) bl[j] = bias[colbase + tx * 8 + j];

#pragma unroll
    for (int i = 0; i < 8; i++) {
        int m  = rowbase + ty * 8 + i;
        int b_ = m >> 11;            // /2048
        int s  = m & 2047;
#pragma unroll
        for (int jj = 0; jj < 2; jj++) {
            int n0    = colbase + tx * 8 + jj * 4;
            int which = n0 >> 10;    // 0=Q 1=K 2=V
            int d     = n0 & 1023;
            int h     = d >> 6;
            int dd    = d & 63;
            float scale = (which == 0) ? 0.125f : 1.0f;
            float4 o;
            o.x = (acc[i][jj * 4 + 0] + bl[jj * 4 + 0]) * scale;
            o.y = (acc[i][jj * 4 + 1] + bl[jj * 4 + 1]) * scale;
            o.z = (acc[i][jj * 4 + 2] + bl[jj * 4 + 2]) * scale;
            o.w = (acc[i][jj * 4 + 3] + bl[jj * 4 + 3]) * scale;
            size_t dst = (size_t)which * PLANE +
                         (((size_t)(b_ * NHEAD + h) * SEQ + s) * HDIM) + dd;
            *(float4*)&g_QKV[dst] = o;
        }
    }
}

// ---------------------------------------------------------------------------
// Flash attention: one block per (b*h, 64-query tile). 256 threads (16x16),
// each thread owns a 4 (rows) x 4 (cols / head-dims) register tile.
// Online softmax; P reuses K's SMEM buffer. K stored transposed [d][col].
// ---------------------------------------------------------------------------
#define KSTR 68   // padded row stride (floats) for Kt/P and V

extern __shared__ float fa_smem[];

__global__ __launch_bounds__(256) void flash_kernel()
{
    float* Qs = fa_smem;                 // [64][64]     4096 floats
    float* Ks = fa_smem + 4096;          // [64][KSTR]   4352 floats (Kt, then P)
    float* Vs = Ks + 64 * KSTR;          // [64][KSTR]   4352 floats

    const int bh  = blockIdx.x;          // 0..63 = b*16+h
    const int qb  = blockIdx.y;          // 0..31
    const int tid = threadIdx.x;
    const int tx  = tid & 15;
    const int ty  = tid >> 4;

    const float* Qg = g_QKV + ((size_t)bh * SEQ + qb * 64) * HDIM;
    const float* Kg = g_QKV + (size_t)PLANE     + (size_t)bh * SEQ * HDIM;
    const float* Vg = g_QKV + (size_t)2 * PLANE + (size_t)bh * SEQ * HDIM;

    // Load Q tile 64x64 (already pre-scaled by 1/8)
#pragma unroll
    for (int it = 0; it < 4; it++) {
        int flat = tid + it * 256;       // float4 idx among 1024
        int r  = flat >> 4;
        int c4 = (flat & 15) * 4;
        *(float4*)&Qs[r * 64 + c4] = *(const float4*)&Qg[r * 64 + c4];
    }

    float m_[4], l_[4], acc[4][4];
#pragma unroll
    for (int i = 0; i < 4; i++) {
        m_[i] = -1e30f; l_[i] = 0.f;
#pragma unroll
        for (int j = 0; j < 4; j++) acc[i][j] = 0.f;
    }

    for (int t = 0; t < SEQ / 64; t++) {
        __syncthreads();                 // previous-iter P/V reads done; Q visible
        // Load K (transposed) and V tiles
#pragma unroll
        for (int it = 0; it < 4; it++) {
            int flat = tid + it * 256;
            int r  = flat >> 4;          // row within tile (seq)
            int c4 = (flat & 15) * 4;    // d offset
            size_t gsrc = ((size_t)t * 64 + r) * HDIM + c4;
            float4 kv = *(const float4*)&Kg[gsrc];
            Ks[(c4 + 0) * KSTR + r] = kv.x;
            Ks[(c4 + 1) * KSTR + r] = kv.y;
            Ks[(c4 + 2) * KSTR + r] = kv.z;
            Ks[(c4 + 3) * KSTR + r] = kv.w;
            float4 vv = *(const float4*)&Vg[gsrc];
            *(float4*)&Vs[r * KSTR + c4] = vv;
        }
        __syncthreads();

        // S = Q K^T (scaled already)
        float S[4][4];
#pragma unroll
        for (int i = 0; i < 4; i++)
#pragma unroll
            for (int j = 0; j < 4; j++) S[i][j] = 0.f;

#pragma unroll 8
        for (int d = 0; d < 64; d++) {
            float4 kv = *(const float4*)&Ks[d * KSTR + tx * 4];
            float a0 = Qs[(ty * 4 + 0) * 64 + d];
            float a1 = Qs[(ty * 4 + 1) * 64 + d];
            float a2 = Qs[(ty * 4 + 2) * 64 + d];
            float a3 = Qs[(ty * 4 + 3) * 64 + d];
            S[0][0] += a0 * kv.x; S[0][1] += a0 * kv.y; S[0][2] += a0 * kv.z; S[0][3] += a0 * kv.w;
            S[1][0] += a1 * kv.x; S[1][1] += a1 * kv.y; S[1][2] += a1 * kv.z; S[1][3] += a1 * kv.w;
            S[2][0] += a2 * kv.x; S[2][1] += a2 * kv.y; S[2][2] += a2 * kv.z; S[2][3] += a2 * kv.w;
            S[3][0] += a3 * kv.x; S[3][1] += a3 * kv.y; S[3][2] += a3 * kv.z; S[3][3] += a3 * kv.w;
        }

        // Online softmax (reduce across tx = low 4 bits of tid)
#pragma unroll
        for (int i = 0; i < 4; i++) {
            float mx = fmaxf(fmaxf(S[i][0], S[i][1]), fmaxf(S[i][2], S[i][3]));
            mx = fmaxf(mx, __shfl_xor_sync(0xffffffffu, mx, 1));
            mx = fmaxf(mx, __shfl_xor_sync(0xffffffffu, mx, 2));
            mx = fmaxf(mx, __shfl_xor_sync(0xffffffffu, mx, 4));
            mx = fmaxf(mx, __shfl_xor_sync(0xffffffffu, mx, 8));
            float mnew = fmaxf(m_[i], mx);
            float corr = __expf(m_[i] - mnew);
            m_[i] = mnew;
            l_[i] *= corr;
            acc[i][0] *= corr; acc[i][1] *= corr; acc[i][2] *= corr; acc[i][3] *= corr;
            float p0 = __expf(S[i][0] - mnew);
            float p1 = __expf(S[i][1] - mnew);
            float p2 = __expf(S[i][2] - mnew);
            float p3 = __expf(S[i][3] - mnew);
            S[i][0] = p0; S[i][1] = p1; S[i][2] = p2; S[i][3] = p3;
            l_[i] += p0 + p1 + p2 + p3;   // per-thread partial (4 cols); reduced at end
        }

        __syncthreads();                 // everyone done reading Ks before P overwrite
#pragma unroll
        for (int i = 0; i < 4; i++)
            *(float4*)&Ks[(ty * 4 + i) * KSTR + tx * 4] =
                make_float4(S[i][0], S[i][1], S[i][2], S[i][3]);
        __syncthreads();

        // O += P @ V   (P lives in Ks buffer)
#pragma unroll 8
        for (int j = 0; j < 64; j++) {
            float4 vv = *(const float4*)&Vs[j * KSTR + tx * 4];
            float p0 = Ks[(ty * 4 + 0) * KSTR + j];
            float p1 = Ks[(ty * 4 + 1) * KSTR + j];
            float p2 = Ks[(ty * 4 + 2) * KSTR + j];
            float p3 = Ks[(ty * 4 + 3) * KSTR + j];
            acc[0][0] += p0 * vv.x; acc[0][1] += p0 * vv.y; acc[0][2] += p0 * vv.z; acc[0][3] += p0 * vv.w;
            acc[1][0] += p1 * vv.x; acc[1][1] += p1 * vv.y; acc[1][2] += p1 * vv.z; acc[1][3] += p1 * vv.w;
            acc[2][0] += p2 * vv.x; acc[2][1] += p2 * vv.y; acc[2][2] += p2 * vv.z; acc[2][3] += p2 * vv.w;
            acc[3][0] += p3 * vv.x; acc[3][1] += p3 * vv.y; acc[3][2] += p3 * vv.z; acc[3][3] += p3 * vv.w;
        }
    }

    // FIX (R1): l_ was only a per-thread partial over this thread's 4 columns,
    // while acc sums over ALL 64 columns. Reduce the denominator across the
    // 16-lane column group before normalizing.
#pragma unroll
    for (int i = 0; i < 4; i++) {
        float l = l_[i];
        l += __shfl_xor_sync(0xffffffffu, l, 1);
        l += __shfl_xor_sync(0xffffffffu, l, 2);
        l += __shfl_xor_sync(0xffffffffu, l, 4);
        l += __shfl_xor_sync(0xffffffffu, l, 8);
        l_[i] = l;
    }

    // Write O: [B,S,D] with head offset
    const int b_ = bh >> 4;
    const int h  = bh & 15;
#pragma unroll
    for (int i = 0; i < 4; i++) {
        float inv = 1.0f / l_[i];
        int s = qb * 64 + ty * 4 + i;
        float4 o = make_float4(acc[i][0] * inv, acc[i][1] * inv,
                               acc[i][2] * inv, acc[i][3] * inv);
        *(float4*)&g_O[((size_t)b_ * SEQ + s) * DIMM + h * HDIM + tx * 4] = o;
    }
}

// ---------------------------------------------------------------------------
// GEMM 2: out = g_O @ W_proj + b_proj  (8192x1024x1024)
// ---------------------------------------------------------------------------
__global__ __launch_bounds__(256) void gemm_proj_kernel(
    const float* __restrict__ W,      // [1024,1024]
    const float* __restrict__ bias,   // [1024]
    float* __restrict__ out)          // [8192,1024]
{
    __shared__ float As[16][132];
    __shared__ float Bs[16][128];

    const int tid = threadIdx.x;
    const int tx  = tid & 15;
    const int ty  = tid >> 4;
    const int rowbase = blockIdx.y * 128;
    const int colbase = blockIdx.x * 128;

    float acc[8][8];
#pragma unroll
    for (int i = 0; i < 8; i++)
#pragma unroll
        for (int j = 0; j < 8; j++) acc[i][j] = 0.f;

    for (int k0 = 0; k0 < DIMM; k0 += 16) {
#pragma unroll
        for (int it = 0; it < 2; it++) {
            int flat = tid + it * 256;
            int r  = flat >> 2;
            int c4 = (flat & 3) * 4;
            float4 v = *(const float4*)&g_O[(size_t)(rowbase + r) * DIMM + k0 + c4];
            As[c4 + 0][r] = v.x;
            As[c4 + 1][r] = v.y;
            As[c4 + 2][r] = v.z;
            As[c4 + 3][r] = v.w;
        }
#pragma unroll
        for (int it = 0; it < 2; it++) {
            int flat = tid + it * 256;
            int r  = flat >> 5;
            int c4 = (flat & 31) * 4;
            *(float4*)&Bs[r][c4] = *(const float4*)&W[(size_t)(k0 + r) * DIMM + colbase + c4];
        }
        __syncthreads();

#pragma unroll
        for (int k = 0; k < 16; k++) {
            float a[8], b[8];
            *(float4*)&a[0] = *(const float4*)&As[k][ty * 8];
            *(float4*)&a[4] = *(const float4*)&As[k][ty * 8 + 4];
            *(float4*)&b[0] = *(const float4*)&Bs[k][tx * 8];
            *(float4*)&b[4] = *(const float4*)&Bs[k][tx * 8 + 4];
#pragma unroll
            for (int i = 0; i < 8; i++)
#pragma unroll
                for (int j = 0; j < 8; j++)
                    acc[i][j] += a[i] * b[j];
        }
        __syncthreads();
    }

    float bl[8];
#pragma unroll
    for (int j = 0; j < 8; j++) bl[j] = bias[colbase + tx * 8 + j];

#pragma unroll
    for (int i = 0; i < 8; i++) {
        int m = rowbase + ty * 8 + i;
#pragma unroll
        for (int jj = 0; jj < 2; jj++) {
            int n0 = colbase + tx * 8 + jj * 4;
            float4 o;
            o.x = acc[i][jj * 4 + 0] + bl[jj * 4 + 0];
            o.y = acc[i][jj * 4 + 1] + bl[jj * 4 + 1];
            o.z = acc[i][jj * 4 + 2] + bl[jj * 4 + 2];
            o.w = acc[i][jj * 4 + 3] + bl[jj * 4 + 3];
            *(float4*)&out[(size_t)m * DIMM + n0] = o;
        }
    }
}

// ---------------------------------------------------------------------------
// Launch
// ---------------------------------------------------------------------------
extern "C" void kernel_launch(void* const* d_in, const int* in_sizes, int n_in,
                              void* d_out, int out_size)
{
    const float* x      = (const float*)d_in[0];
    const float* W_qkv  = (const float*)d_in[1];
    const float* b_qkv  = (const float*)d_in[2];
    const float* W_proj = (const float*)d_in[3];
    const float* b_proj = (const float*)d_in[4];
    float* out = (float*)d_out;

    // GEMM1: QKV projection + scatter
    {
        dim3 grid(NQKV / 128, MTOK / 128);   // (24, 64)
        gemm_qkv_kernel<<<grid, 256>>>(x, W_qkv, b_qkv);
    }

    // Flash attention
    {
        const int smem_bytes = (4096 + 2 * 64 * KSTR) * sizeof(float);  // 51200
        cudaFuncSetAttribute(flash_kernel,
                             cudaFuncAttributeMaxDynamicSharedMemorySize, smem_bytes);
        dim3 grid(BATCH * NHEAD, SEQ / 64);  // (64, 32)
        flash_kernel<<<grid, 256, smem_bytes>>>();
    }

    // GEMM2: output projection
    {
        dim3 grid(DIMM / 128, MTOK / 128);   // (8, 64)
        gemm_proj_kernel<<<grid, 256>>>(W_proj, b_proj, out);
    }
}

// round 5
// speedup vs baseline: 2.3446x; 2.3446x over previous
#include <cuda_runtime.h>
#include <cstdint>

// Problem constants
#define DIMM   1024
#define BATCH  4
#define SEQ    2048
#define NHEAD  16
#define HDIM   64
#define MTOK   (BATCH*SEQ)        // 8192
#define NQKV   (3*DIMM)           // 3072
#define PLANE  (BATCH*NHEAD*SEQ*HDIM)  // 8388608 floats per Q/K/V plane

// Scratch (device globals: allocation-free per harness rules)
__device__ float g_QKV[3ULL * PLANE];            // [3][B][H][S][hd]
__device__ float g_O[(size_t)MTOK * DIMM];       // [B,S,D] attention output

// ---------------------------------------------------------------------------
// tf32 helpers
// ---------------------------------------------------------------------------
__device__ __forceinline__ unsigned f2tf(float x) {
    unsigned u;
    asm("cvt.rna.tf32.f32 %0, %1;" : "=r"(u) : "f"(x));
    return u;
}

// D = A(16x8, row) * B(8x8, col) + D, tf32 inputs, f32 accum.
// lane: g = lane>>2 (group/row), t = lane&3.
// a0=[g][t] a1=[g+8][t] a2=[g][t+4] a3=[g+8][t+4]
// b0=[k=t][n=g] b1=[k=t+4][n=g]
// c0=[g][2t] c1=[g][2t+1] c2=[g+8][2t] c3=[g+8][2t+1]
__device__ __forceinline__ void mma_tf32(float* c, const unsigned* a, unsigned b0, unsigned b1) {
    asm volatile(
        "mma.sync.aligned.m16n8k8.row.col.f32.tf32.tf32.f32 "
        "{%0,%1,%2,%3}, {%4,%5,%6,%7}, {%8,%9}, {%0,%1,%2,%3};"
        : "+f"(c[0]), "+f"(c[1]), "+f"(c[2]), "+f"(c[3])
        : "r"(a[0]), "r"(a[1]), "r"(a[2]), "r"(a[3]), "r"(b0), "r"(b1));
}

// ---------------------------------------------------------------------------
// Tensor-core GEMM: C[128x128 tile] = A @ W (+bias).  BK=32, 256 threads,
// 8 warps in 2(m) x 4(n) arrangement, each warp 64x32 via m16n8k8 tf32.
// QKV=true : A=x [8192,1024], W=[1024,3072], scatter epilogue into g_QKV
//            with Q pre-scaled by 0.125.
// QKV=false: A=g_O (read via device symbol — NOT passed from host!),
//            W=[1024,1024], plain epilogue into out.
// ---------------------------------------------------------------------------
template<bool QKV>
__global__ __launch_bounds__(256) void gemm_mma_kernel(
    const float* __restrict__ A_in, const float* __restrict__ W,
    const float* __restrict__ bias, float* __restrict__ out)
{
    constexpr int NC = QKV ? NQKV : DIMM;
    // R3 FIX: g_O must be resolved in DEVICE code; host-side g_O is a shadow.
    const float* __restrict__ A = QKV ? A_in : (const float*)g_O;

    __shared__ unsigned As[128][36];   // [m][k], stride 36 -> frag bank = 4g+t (cf-free)
    __shared__ unsigned Bs[32][136];   // [k][n], stride 136 -> frag bank = 8t+g (cf-free)

    const int tid  = threadIdx.x;
    const int lane = tid & 31;
    const int warp = tid >> 5;
    const int g  = lane >> 2;
    const int t4 = lane & 3;
    const int m0 = (warp & 1) * 64;
    const int n0 = (warp >> 1) * 32;
    const int rowbase = blockIdx.y * 128;
    const int colbase = blockIdx.x * 128;

    float acc[4][4][4];
#pragma unroll
    for (int mi = 0; mi < 4; mi++)
#pragma unroll
        for (int ni = 0; ni < 4; ni++)
#pragma unroll
            for (int r = 0; r < 4; r++) acc[mi][ni][r] = 0.f;

    for (int k0 = 0; k0 < DIMM; k0 += 32) {
        // A tile 128x32 (1024 float4)
#pragma unroll
        for (int it = 0; it < 4; it++) {
            int flat = tid + it * 256;
            int r  = flat >> 3;
            int c4 = (flat & 7) * 4;
            float4 v = *(const float4*)&A[(size_t)(rowbase + r) * DIMM + k0 + c4];
            uint4 u = make_uint4(f2tf(v.x), f2tf(v.y), f2tf(v.z), f2tf(v.w));
            *(uint4*)&As[r][c4] = u;
        }
        // B tile 32x128 (1024 float4)
#pragma unroll
        for (int it = 0; it < 4; it++) {
            int flat = tid + it * 256;
            int r  = flat >> 5;
            int c4 = (flat & 31) * 4;
            float4 v = *(const float4*)&W[(size_t)(k0 + r) * NC + colbase + c4];
            uint4 u = make_uint4(f2tf(v.x), f2tf(v.y), f2tf(v.z), f2tf(v.w));
            *(uint4*)&Bs[r][c4] = u;
        }
        __syncthreads();

#pragma unroll
        for (int ks = 0; ks < 4; ks++) {
            const int kk = ks * 8;
            unsigned af[4][4];
#pragma unroll
            for (int mi = 0; mi < 4; mi++) {
                int row = m0 + mi * 16 + g;
                af[mi][0] = As[row    ][kk + t4];
                af[mi][1] = As[row + 8][kk + t4];
                af[mi][2] = As[row    ][kk + t4 + 4];
                af[mi][3] = As[row + 8][kk + t4 + 4];
            }
            unsigned bf[4][2];
#pragma unroll
            for (int ni = 0; ni < 4; ni++) {
                int col = n0 + ni * 8 + g;
                bf[ni][0] = Bs[kk + t4    ][col];
                bf[ni][1] = Bs[kk + t4 + 4][col];
            }
#pragma unroll
            for (int mi = 0; mi < 4; mi++)
#pragma unroll
                for (int ni = 0; ni < 4; ni++)
                    mma_tf32(acc[mi][ni], af[mi], bf[ni][0], bf[ni][1]);
        }
        __syncthreads();
    }

    // Epilogue
#pragma unroll
    for (int mi = 0; mi < 4; mi++) {
#pragma unroll
        for (int half = 0; half < 2; half++) {      // row g / g+8
            int m = rowbase + m0 + mi * 16 + g + half * 8;
#pragma unroll
            for (int ni = 0; ni < 4; ni++) {
                int c  = colbase + n0 + ni * 8 + 2 * t4;
                float v0 = acc[mi][ni][half * 2 + 0] + bias[c];
                float v1 = acc[mi][ni][half * 2 + 1] + bias[c + 1];
                if (QKV) {
                    int which = c >> 10;
                    int d     = c & 1023;
                    int h     = d >> 6;
                    int dd    = d & 63;
                    float sc  = (which == 0) ? 0.125f : 1.0f;
                    int b_ = m >> 11;
                    int s  = m & 2047;
                    size_t dst = (size_t)which * PLANE +
                                 (((size_t)(b_ * NHEAD + h) * SEQ + s) * HDIM) + dd;
                    *(float2*)&g_QKV[dst] = make_float2(v0 * sc, v1 * sc);
                } else {
                    *(float2*)&out[(size_t)m * DIMM + c] = make_float2(v0, v1);
                }
            }
        }
    }
}

// ---------------------------------------------------------------------------
// Flash attention with tf32 mma. CTA = (bh, 128-query tile), 8 warps, each
// warp owns 16 query rows. Q fragments live in registers for the whole KV
// loop. K tile used directly as col-major B; V transposed in SMEM; P goes
// through per-warp SMEM to re-fragment from C-layout to A-layout.
// ---------------------------------------------------------------------------
#define KS_STR 68
#define VT_STR 69
#define PS_STR 68

extern __shared__ float fa_smem[];

__global__ __launch_bounds__(256) void flash_mma_kernel()
{
    float* Ks = fa_smem;                      // [64][KS_STR]  K tile, tf32 bits
    float* Vt = fa_smem + 64 * KS_STR;        // [64][VT_STR]  V^T tile, tf32 bits
    float* Ps = Vt + 64 * VT_STR;             // [128][PS_STR] Q staging, then per-warp P

    const int bh  = blockIdx.x;               // b*16 + h
    const int qb  = blockIdx.y;               // 0..15 (128-query tiles)
    const int tid = threadIdx.x;
    const int lane = tid & 31;
    const int warp = tid >> 5;
    const int g  = lane >> 2;
    const int t4 = lane & 3;
    const int w16 = warp * 16;

    const float* Qg = g_QKV + ((size_t)bh * SEQ + qb * 128) * HDIM;
    const float* Kg = g_QKV + (size_t)PLANE     + (size_t)bh * SEQ * HDIM;
    const float* Vg = g_QKV + (size_t)2 * PLANE + (size_t)bh * SEQ * HDIM;

    // Stage Q (128x64) into Ps, then preload A-fragments (Q pre-scaled 0.125)
#pragma unroll
    for (int it = 0; it < 8; it++) {
        int flat = tid + it * 256;            // 2048 float4
        int r  = flat >> 4;
        int c4 = (flat & 15) * 4;
        *(float4*)&Ps[r * PS_STR + c4] = *(const float4*)&Qg[(size_t)r * HDIM + c4];
    }
    __syncthreads();

    unsigned aq[8][4];
#pragma unroll
    for (int ks = 0; ks < 8; ks++) {
        int kk = ks * 8;
        aq[ks][0] = f2tf(Ps[(w16 + g    ) * PS_STR + kk + t4]);
        aq[ks][1] = f2tf(Ps[(w16 + g + 8) * PS_STR + kk + t4]);
        aq[ks][2] = f2tf(Ps[(w16 + g    ) * PS_STR + kk + t4 + 4]);
        aq[ks][3] = f2tf(Ps[(w16 + g + 8) * PS_STR + kk + t4 + 4]);
    }

    float m_[2] = {-1e30f, -1e30f};
    float l_[2] = {0.f, 0.f};
    float o[8][4];
#pragma unroll
    for (int ni = 0; ni < 8; ni++)
#pragma unroll
        for (int r = 0; r < 4; r++) o[ni][r] = 0.f;

    for (int kt = 0; kt < SEQ / 64; kt++) {
        __syncthreads();                      // prev-iter Ks/Vt reads (and Q stage) done
        // Load K tile [64][64] (tf32 bits) and V^T tile
#pragma unroll
        for (int it = 0; it < 4; it++) {
            int flat = tid + it * 256;        // 1024 float4
            int r  = flat >> 4;
            int c4 = (flat & 15) * 4;
            size_t gsrc = ((size_t)kt * 64 + r) * HDIM + c4;
            float4 kv4 = *(const float4*)&Kg[gsrc];
            uint4 ku = make_uint4(f2tf(kv4.x), f2tf(kv4.y), f2tf(kv4.z), f2tf(kv4.w));
            *(uint4*)&Ks[r * KS_STR + c4] = ku;
            float4 vv4 = *(const float4*)&Vg[gsrc];
            Vt[(c4 + 0) * VT_STR + r] = __uint_as_float(f2tf(vv4.x));
            Vt[(c4 + 1) * VT_STR + r] = __uint_as_float(f2tf(vv4.y));
            Vt[(c4 + 2) * VT_STR + r] = __uint_as_float(f2tf(vv4.z));
            Vt[(c4 + 3) * VT_STR + r] = __uint_as_float(f2tf(vv4.w));
        }
        __syncthreads();

        // S = Q @ K^T  (16 q-rows x 64 kv-cols per warp)
        float s[8][4];
#pragma unroll
        for (int ni = 0; ni < 8; ni++)
#pragma unroll
            for (int r = 0; r < 4; r++) s[ni][r] = 0.f;

#pragma unroll
        for (int ni = 0; ni < 8; ni++) {
            const float* kb = &Ks[(size_t)(ni * 8 + g) * KS_STR];
#pragma unroll
            for (int ks = 0; ks < 8; ks++) {
                unsigned b0 = __float_as_uint(kb[ks * 8 + t4]);
                unsigned b1 = __float_as_uint(kb[ks * 8 + t4 + 4]);
                mma_tf32(s[ni], aq[ks], b0, b1);
            }
        }

        // Online softmax for rows g and g+8 (reduce over the 4 t-lanes)
        float mx0 = -1e30f, mx1 = -1e30f;
#pragma unroll
        for (int ni = 0; ni < 8; ni++) {
            mx0 = fmaxf(mx0, fmaxf(s[ni][0], s[ni][1]));
            mx1 = fmaxf(mx1, fmaxf(s[ni][2], s[ni][3]));
        }
        mx0 = fmaxf(mx0, __shfl_xor_sync(0xffffffffu, mx0, 1));
        mx0 = fmaxf(mx0, __shfl_xor_sync(0xffffffffu, mx0, 2));
        mx1 = fmaxf(mx1, __shfl_xor_sync(0xffffffffu, mx1, 1));
        mx1 = fmaxf(mx1, __shfl_xor_sync(0xffffffffu, mx1, 2));

        float mn0 = fmaxf(m_[0], mx0);
        float mn1 = fmaxf(m_[1], mx1);
        float corr0 = __expf(m_[0] - mn0);
        float corr1 = __expf(m_[1] - mn1);
        m_[0] = mn0; m_[1] = mn1;

        float lp0 = 0.f, lp1 = 0.f;
#pragma unroll
        for (int ni = 0; ni < 8; ni++) {
            s[ni][0] = __expf(s[ni][0] - mn0);
            s[ni][1] = __expf(s[ni][1] - mn0);
            s[ni][2] = __expf(s[ni][2] - mn1);
            s[ni][3] = __expf(s[ni][3] - mn1);
            lp0 += s[ni][0] + s[ni][1];
            lp1 += s[ni][2] + s[ni][3];
            o[ni][0] *= corr0; o[ni][1] *= corr0;
            o[ni][2] *= corr1; o[ni][3] *= corr1;
        }
        lp0 += __shfl_xor_sync(0xffffffffu, lp0, 1);
        lp0 += __shfl_xor_sync(0xffffffffu, lp0, 2);
        lp1 += __shfl_xor_sync(0xffffffffu, lp1, 1);
        lp1 += __shfl_xor_sync(0xffffffffu, lp1, 2);
        l_[0] = l_[0] * corr0 + lp0;
        l_[1] = l_[1] * corr1 + lp1;

        // Store P (tf32 bits) into this warp's Ps rows, re-fragment as A
        __syncwarp();
#pragma unroll
        for (int ni = 0; ni < 8; ni++) {
            int c = ni * 8 + 2 * t4;
            *(float2*)&Ps[(w16 + g    ) * PS_STR + c] =
                make_float2(__uint_as_float(f2tf(s[ni][0])), __uint_as_float(f2tf(s[ni][1])));
            *(float2*)&Ps[(w16 + g + 8) * PS_STR + c] =
                make_float2(__uint_as_float(f2tf(s[ni][2])), __uint_as_float(f2tf(s[ni][3])));
        }
        __syncwarp();

        // O += P @ V
#pragma unroll
        for (int ks = 0; ks < 8; ks++) {
            int kk = ks * 8;
            unsigned ap[4];
            ap[0] = __float_as_uint(Ps[(w16 + g    ) * PS_STR + kk + t4]);
            ap[1] = __float_as_uint(Ps[(w16 + g + 8) * PS_STR + kk + t4]);
            ap[2] = __float_as_uint(Ps[(w16 + g    ) * PS_STR + kk + t4 + 4]);
            ap[3] = __float_as_uint(Ps[(w16 + g + 8) * PS_STR + kk + t4 + 4]);
#pragma unroll
            for (int ni = 0; ni < 8; ni++) {
                unsigned b0 = __float_as_uint(Vt[(size_t)(ni * 8 + g) * VT_STR + kk + t4]);
                unsigned b1 = __float_as_uint(Vt[(size_t)(ni * 8 + g) * VT_STR + kk + t4 + 4]);
                mma_tf32(o[ni], ap, b0, b1);
            }
        }
    }

    // Normalize and write O: [B,S,D], head offset h*64
    const int b_ = bh >> 4;
    const int h  = bh & 15;
    float inv0 = 1.0f / l_[0];
    float inv1 = 1.0f / l_[1];
    int s0 = qb * 128 + w16 + g;
    int s1 = s0 + 8;
#pragma unroll
    for (int ni = 0; ni < 8; ni++) {
        int d2 = ni * 8 + 2 * t4;
        *(float2*)&g_O[((size_t)b_ * SEQ + s0) * DIMM + h * HDIM + d2] =
            make_float2(o[ni][0] * inv0, o[ni][1] * inv0);
        *(float2*)&g_O[((size_t)b_ * SEQ + s1) * DIMM + h * HDIM + d2] =
            make_float2(o[ni][2] * inv1, o[ni][3] * inv1);
    }
}

// ---------------------------------------------------------------------------
// Launch
// ---------------------------------------------------------------------------
extern "C" void kernel_launch(void* const* d_in, const int* in_sizes, int n_in,
                              void* d_out, int out_size)
{
    const float* x      = (const float*)d_in[0];
    const float* W_qkv  = (const float*)d_in[1];
    const float* b_qkv  = (const float*)d_in[2];
    const float* W_proj = (const float*)d_in[3];
    const float* b_proj = (const float*)d_in[4];
    float* out = (float*)d_out;

    // GEMM1: QKV projection + scatter (tensor cores, tf32)
    {
        dim3 grid(NQKV / 128, MTOK / 128);   // (24, 64)
        gemm_mma_kernel<true><<<grid, 256>>>(x, W_qkv, b_qkv, nullptr);
    }

    // Flash attention (tensor cores, tf32)
    {
        const int smem_bytes = (64 * KS_STR + 64 * VT_STR + 128 * PS_STR) * (int)sizeof(float);
        cudaFuncSetAttribute(flash_mma_kernel,
                             cudaFuncAttributeMaxDynamicSharedMemorySize, smem_bytes);
        dim3 grid(BATCH * NHEAD, SEQ / 128); // (64, 16)
        flash_mma_kernel<<<grid, 256, smem_bytes>>>();
    }

    // GEMM2: output projection (tensor cores, tf32; A = g_O resolved in device code)
    {
        dim3 grid(DIMM / 128, MTOK / 128);   // (8, 64)
        gemm_mma_kernel<false><<<grid, 256>>>(nullptr, W_proj, b_proj, out);
    }
}

// round 8
// speedup vs baseline: 3.6668x; 1.5639x over previous
#include <cuda_runtime.h>
#include <cstdint>

// Problem constants
#define DIMM   1024
#define BATCH  4
#define SEQ    2048
#define NHEAD  16
#define HDIM   64
#define MTOK   (BATCH*SEQ)        // 8192
#define NQKV   (3*DIMM)           // 3072
#define PLANE  (BATCH*NHEAD*SEQ*HDIM)  // 8388608 floats per Q/K/V plane

// Q pre-scale: 1/sqrt(64) * log2(e)  (softmax done in exp2 domain)
#define QSCALE 0.18033688011112042f

// Scratch (device globals: allocation-free per harness rules)
__device__ float g_QKV[3ULL * PLANE];            // [3][B][H][S][hd] (tf32-rounded)
__device__ float g_O[(size_t)MTOK * DIMM];       // [B,S,D] attention out (tf32-rounded)
__device__ float g_x [(size_t)MTOK * DIMM];      // tf32-rounded x
__device__ float g_Wq[(size_t)DIMM * NQKV];      // tf32-rounded W_qkv
__device__ float g_Wp[(size_t)DIMM * DIMM];      // tf32-rounded W_proj

// ---------------------------------------------------------------------------
// helpers
// ---------------------------------------------------------------------------
__device__ __forceinline__ float tfr(float x) {   // round-to-nearest tf32, as float
    unsigned u;
    asm("cvt.rna.tf32.f32 %0, %1;" : "=r"(u) : "f"(x));
    return __uint_as_float(u);
}

// mma.m16n8k8 tf32: operands already tf32-rounded -> HW truncation is lossless.
__device__ __forceinline__ void mma_tf32(float* c, const unsigned* a, unsigned b0, unsigned b1) {
    asm volatile(
        "mma.sync.aligned.m16n8k8.row.col.f32.tf32.tf32.f32 "
        "{%0,%1,%2,%3}, {%4,%5,%6,%7}, {%8,%9}, {%0,%1,%2,%3};"
        : "+f"(c[0]), "+f"(c[1]), "+f"(c[2]), "+f"(c[3])
        : "r"(a[0]), "r"(a[1]), "r"(a[2]), "r"(a[3]), "r"(b0), "r"(b1));
}

__device__ __forceinline__ void cp16(void* smem, const void* gmem) {
    unsigned sa = (unsigned)__cvta_generic_to_shared(smem);
    asm volatile("cp.async.cg.shared.global [%0], [%1], 16;" :: "r"(sa), "l"(gmem));
}
#define CP_COMMIT()     asm volatile("cp.async.commit_group;")
#define CP_WAIT(n)      asm volatile("cp.async.wait_group %0;" :: "n"(n))

// ---------------------------------------------------------------------------
// Pre-pass: tf32-round inputs into device-global copies. WHICH: 0=x 1=Wq 2=Wp
// ---------------------------------------------------------------------------
template<int WHICH>
__global__ void round_prepass(const float* __restrict__ src, int n4)
{
    float* dst = (WHICH == 0) ? g_x : (WHICH == 1) ? g_Wq : g_Wp;
    int i = blockIdx.x * blockDim.x + threadIdx.x;
    if (i < n4) {
        float4 v = ((const float4*)src)[i];
        v.x = tfr(v.x); v.y = tfr(v.y); v.z = tfr(v.z); v.w = tfr(v.w);
        ((float4*)dst)[i] = v;
    }
}

// ---------------------------------------------------------------------------
// Tensor-core GEMM, cp.async double-buffered. C[128x128] = A @ W (+bias).
// BK=32, 256 threads, 8 warps 2(m) x 4(n), each warp 64x32 via m16n8k8.
// All operand tensors are pre-rounded to tf32 -> raw-bit feed is exact.
// QKV=true : A=g_x, W=g_Wq, scatter epilogue -> g_QKV (Q scaled, all rounded)
// QKV=false: A=g_O, W=g_Wp, epilogue -> out (fp32, no rounding needed)
// ---------------------------------------------------------------------------
#define AS_STR 36     // frag addr mod32 = 4g+t  (conflict-free)
#define BS_STR 136    // frag addr mod32 = 8t+g  (conflict-free)
#define AS_WORDS (128*AS_STR)   // 4608
#define BS_WORDS (32*BS_STR)    // 4352

extern __shared__ unsigned dyn_smem[];

template<bool QKV>
__global__ __launch_bounds__(256) void gemm_mma_kernel(
    const float* __restrict__ bias, float* __restrict__ out)
{
    constexpr int NC = QKV ? NQKV : DIMM;
    const float* __restrict__ A = QKV ? (const float*)g_x : (const float*)g_O;
    const float* __restrict__ W = QKV ? (const float*)g_Wq : (const float*)g_Wp;

    unsigned* AsB = dyn_smem;                  // [2][AS_WORDS]
    unsigned* BsB = dyn_smem + 2 * AS_WORDS;   // [2][BS_WORDS]

    const int tid  = threadIdx.x;
    const int lane = tid & 31;
    const int warp = tid >> 5;
    const int g  = lane >> 2;
    const int t4 = lane & 3;
    const int m0 = (warp & 1) * 64;
    const int n0 = (warp >> 1) * 32;
    const int rowbase = blockIdx.y * 128;
    const int colbase = blockIdx.x * 128;

    auto load_tile = [&](int buf, int k0) {
        unsigned* As = AsB + buf * AS_WORDS;
        unsigned* Bs = BsB + buf * BS_WORDS;
#pragma unroll
        for (int it = 0; it < 4; it++) {
            int flat = tid + it * 256;
            int r  = flat >> 3;
            int c4 = (flat & 7) * 4;
            cp16(&As[r * AS_STR + c4], &A[(size_t)(rowbase + r) * DIMM + k0 + c4]);
        }
#pragma unroll
        for (int it = 0; it < 4; it++) {
            int flat = tid + it * 256;
            int r  = flat >> 5;
            int c4 = (flat & 31) * 4;
            cp16(&Bs[r * BS_STR + c4], &W[(size_t)(k0 + r) * NC + colbase + c4]);
        }
    };

    float acc[4][4][4];
#pragma unroll
    for (int mi = 0; mi < 4; mi++)
#pragma unroll
        for (int ni = 0; ni < 4; ni++)
#pragma unroll
            for (int r = 0; r < 4; r++) acc[mi][ni][r] = 0.f;

    load_tile(0, 0);
    CP_COMMIT();

    constexpr int NT = DIMM / 32;   // 32 k-tiles
#pragma unroll 1
    for (int i = 0; i < NT; i++) {
        if (i + 1 < NT) {
            load_tile((i + 1) & 1, (i + 1) * 32);
            CP_COMMIT();
            CP_WAIT(1);
        } else {
            CP_WAIT(0);
        }
        __syncthreads();

        const unsigned* As = AsB + (i & 1) * AS_WORDS;
        const unsigned* Bs = BsB + (i & 1) * BS_WORDS;
#pragma unroll
        for (int ks = 0; ks < 4; ks++) {
            const int kk = ks * 8;
            unsigned af[4][4];
#pragma unroll
            for (int mi = 0; mi < 4; mi++) {
                int row = m0 + mi * 16 + g;
                af[mi][0] = As[(row    ) * AS_STR + kk + t4];
                af[mi][1] = As[(row + 8) * AS_STR + kk + t4];
                af[mi][2] = As[(row    ) * AS_STR + kk + t4 + 4];
                af[mi][3] = As[(row + 8) * AS_STR + kk + t4 + 4];
            }
            unsigned bf[4][2];
#pragma unroll
            for (int ni = 0; ni < 4; ni++) {
                int col = n0 + ni * 8 + g;
                bf[ni][0] = Bs[(kk + t4    ) * BS_STR + col];
                bf[ni][1] = Bs[(kk + t4 + 4) * BS_STR + col];
            }
#pragma unroll
            for (int mi = 0; mi < 4; mi++)
#pragma unroll
                for (int ni = 0; ni < 4; ni++)
                    mma_tf32(acc[mi][ni], af[mi], bf[ni][0], bf[ni][1]);
        }
        __syncthreads();
    }

    // Epilogue
#pragma unroll
    for (int mi = 0; mi < 4; mi++) {
#pragma unroll
        for (int half = 0; half < 2; half++) {
            int m = rowbase + m0 + mi * 16 + g + half * 8;
#pragma unroll
            for (int ni = 0; ni < 4; ni++) {
                int c  = colbase + n0 + ni * 8 + 2 * t4;
                float v0 = acc[mi][ni][half * 2 + 0] + bias[c];
                float v1 = acc[mi][ni][half * 2 + 1] + bias[c + 1];
                if (QKV) {
                    int which = c >> 10;
                    int d     = c & 1023;
                    int h     = d >> 6;
                    int dd    = d & 63;
                    float sc  = (which == 0) ? QSCALE : 1.0f;
                    int b_ = m >> 11;
                    int s  = m & 2047;
                    size_t dst = (size_t)which * PLANE +
                                 (((size_t)(b_ * NHEAD + h) * SEQ + s) * HDIM) + dd;
                    // tf32-round Q/K/V here so downstream raw-bit MMA is exact
                    *(float2*)&g_QKV[dst] = make_float2(tfr(v0 * sc), tfr(v1 * sc));
                } else {
                    *(float2*)&out[(size_t)m * DIMM + c] = make_float2(v0, v1);
                }
            }
        }
    }
}

// ---------------------------------------------------------------------------
// Flash attention, cp.async double-buffered K/V (row-major, no transpose),
// raw-bit tf32 (operands pre-rounded), exp2-domain softmax.
// CTA = (bh, 128-query tile), 8 warps x 16 query rows.
// ---------------------------------------------------------------------------
#define KS_STR 68     // K frag addr mod32 = 4g+t (conflict-free)
#define VS_STR 72     // V frag addr mod32 = 8t+g (conflict-free)
#define PS_STR 68
#define KS_WORDS (64*KS_STR)    // 4352
#define VS_WORDS (64*VS_STR)    // 4608

__global__ __launch_bounds__(256) void flash_mma_kernel()
{
    unsigned* KsB = dyn_smem;                     // [2][KS_WORDS]
    unsigned* VsB = dyn_smem + 2 * KS_WORDS;      // [2][VS_WORDS]
    float*    Ps  = (float*)(dyn_smem + 2 * KS_WORDS + 2 * VS_WORDS);  // [128][PS_STR]

    const int bh  = blockIdx.x;
    const int qb  = blockIdx.y;
    const int tid = threadIdx.x;
    const int lane = tid & 31;
    const int warp = tid >> 5;
    const int g  = lane >> 2;
    const int t4 = lane & 3;
    const int w16 = warp * 16;

    const float* Qg = g_QKV + ((size_t)bh * SEQ + qb * 128) * HDIM;
    const float* Kg = g_QKV + (size_t)PLANE     + (size_t)bh * SEQ * HDIM;
    const float* Vg = g_QKV + (size_t)2 * PLANE + (size_t)bh * SEQ * HDIM;

    auto load_kv = [&](int buf, int kt) {
        unsigned* Ks = KsB + buf * KS_WORDS;
        unsigned* Vs = VsB + buf * VS_WORDS;
#pragma unroll
        for (int it = 0; it < 4; it++) {
            int flat = tid + it * 256;
            int r  = flat >> 4;
            int c4 = (flat & 15) * 4;
            size_t gsrc = ((size_t)kt * 64 + r) * HDIM + c4;
            cp16(&Ks[r * KS_STR + c4], &Kg[gsrc]);
            cp16(&Vs[r * VS_STR + c4], &Vg[gsrc]);
        }
    };

    // Prefetch KV tile 0 first so it overlaps Q staging
    load_kv(0, 0);
    CP_COMMIT();

    // Stage Q (128x64; pre-rounded + pre-scaled in GEMM1)
#pragma unroll
    for (int it = 0; it < 8; it++) {
        int flat = tid + it * 256;
        int r  = flat >> 4;
        int c4 = (flat & 15) * 4;
        *(float4*)&Ps[r * PS_STR + c4] = *(const float4*)&Qg[(size_t)r * HDIM + c4];
    }
    __syncthreads();

    unsigned aq[8][4];
#pragma unroll
    for (int ks = 0; ks < 8; ks++) {
        int kk = ks * 8;
        aq[ks][0] = __float_as_uint(Ps[(w16 + g    ) * PS_STR + kk + t4]);
        aq[ks][1] = __float_as_uint(Ps[(w16 + g + 8) * PS_STR + kk + t4]);
        aq[ks][2] = __float_as_uint(Ps[(w16 + g    ) * PS_STR + kk + t4 + 4]);
        aq[ks][3] = __float_as_uint(Ps[(w16 + g + 8) * PS_STR + kk + t4 + 4]);
    }

    float m_[2] = {-1e30f, -1e30f};
    float l_[2] = {0.f, 0.f};
    float o[8][4];
#pragma unroll
    for (int ni = 0; ni < 8; ni++)
#pragma unroll
        for (int r = 0; r < 4; r++) o[ni][r] = 0.f;

    constexpr int NT = SEQ / 64;   // 32 KV tiles
#pragma unroll 1
    for (int kt = 0; kt < NT; kt++) {
        if (kt + 1 < NT) {
            load_kv((kt + 1) & 1, kt + 1);
            CP_COMMIT();
            CP_WAIT(1);
        } else {
            CP_WAIT(0);
        }
        __syncthreads();

        const unsigned* Ks = KsB + (kt & 1) * KS_WORDS;
        const unsigned* Vs = VsB + (kt & 1) * VS_WORDS;

        // S = Q @ K^T (log2-domain scores; Q pre-scaled)
        float s[8][4];
#pragma unroll
        for (int ni = 0; ni < 8; ni++)
#pragma unroll
            for (int r = 0; r < 4; r++) s[ni][r] = 0.f;

#pragma unroll
        for (int ni = 0; ni < 8; ni++) {
            const unsigned* kb = &Ks[(size_t)(ni * 8 + g) * KS_STR];
#pragma unroll
            for (int ks = 0; ks < 8; ks++) {
                mma_tf32(s[ni], aq[ks], kb[ks * 8 + t4], kb[ks * 8 + t4 + 4]);
            }
        }

        // Online softmax (exp2 domain), rows g and g+8, reduce over 4 t-lanes
        float mx0 = -1e30f, mx1 = -1e30f;
#pragma unroll
        for (int ni = 0; ni < 8; ni++) {
            mx0 = fmaxf(mx0, fmaxf(s[ni][0], s[ni][1]));
            mx1 = fmaxf(mx1, fmaxf(s[ni][2], s[ni][3]));
        }
        mx0 = fmaxf(mx0, __shfl_xor_sync(0xffffffffu, mx0, 1));
        mx0 = fmaxf(mx0, __shfl_xor_sync(0xffffffffu, mx0, 2));
        mx1 = fmaxf(mx1, __shfl_xor_sync(0xffffffffu, mx1, 1));
        mx1 = fmaxf(mx1, __shfl_xor_sync(0xffffffffu, mx1, 2));

        float mn0 = fmaxf(m_[0], mx0);
        float mn1 = fmaxf(m_[1], mx1);
        float corr0 = exp2f(m_[0] - mn0);
        float corr1 = exp2f(m_[1] - mn1);
        m_[0] = mn0; m_[1] = mn1;

        // P rounded to tf32 immediately; denominator summed from the SAME
        // rounded values so numerator/denominator stay consistent.
        float lp0 = 0.f, lp1 = 0.f;
#pragma unroll
        for (int ni = 0; ni < 8; ni++) {
            s[ni][0] = tfr(exp2f(s[ni][0] - mn0));
            s[ni][1] = tfr(exp2f(s[ni][1] - mn0));
            s[ni][2] = tfr(exp2f(s[ni][2] - mn1));
            s[ni][3] = tfr(exp2f(s[ni][3] - mn1));
            lp0 += s[ni][0] + s[ni][1];
            lp1 += s[ni][2] + s[ni][3];
            o[ni][0] *= corr0; o[ni][1] *= corr0;
            o[ni][2] *= corr1; o[ni][3] *= corr1;
        }
        lp0 += __shfl_xor_sync(0xffffffffu, lp0, 1);
        lp0 += __shfl_xor_sync(0xffffffffu, lp0, 2);
        lp1 += __shfl_xor_sync(0xffffffffu, lp1, 1);
        lp1 += __shfl_xor_sync(0xffffffffu, lp1, 2);
        l_[0] = l_[0] * corr0 + lp0;
        l_[1] = l_[1] * corr1 + lp1;

        // Store P into this warp's Ps rows (C-layout -> A-layout re-fragment)
        __syncwarp();
#pragma unroll
        for (int ni = 0; ni < 8; ni++) {
            int c = ni * 8 + 2 * t4;
            *(float2*)&Ps[(w16 + g    ) * PS_STR + c] = make_float2(s[ni][0], s[ni][1]);
            *(float2*)&Ps[(w16 + g + 8) * PS_STR + c] = make_float2(s[ni][2], s[ni][3]);
        }
        __syncwarp();

        // O += P @ V   (V row-major; B-frag read direct, conflict-free)
#pragma unroll
        for (int ks = 0; ks < 8; ks++) {
            int kk = ks * 8;
            unsigned ap[4];
            ap[0] = __float_as_uint(Ps[(w16 + g    ) * PS_STR + kk + t4]);
            ap[1] = __float_as_uint(Ps[(w16 + g + 8) * PS_STR + kk + t4]);
            ap[2] = __float_as_uint(Ps[(w16 + g    ) * PS_STR + kk + t4 + 4]);
            ap[3] = __float_as_uint(Ps[(w16 + g + 8) * PS_STR + kk + t4 + 4]);
#pragma unroll
            for (int ni = 0; ni < 8; ni++) {
                unsigned b0 = Vs[(size_t)(kk + t4    ) * VS_STR + ni * 8 + g];
                unsigned b1 = Vs[(size_t)(kk + t4 + 4) * VS_STR + ni * 8 + g];
                mma_tf32(o[ni], ap, b0, b1);
            }
        }
        __syncthreads();   // all warps done with Ks/Vs[kt&1] before it is refilled
    }

    // Normalize, tf32-round (g_O feeds GEMM2 raw-bit), write [B,S,D]
    const int b_ = bh >> 4;
    const int h  = bh & 15;
    float inv0 = 1.0f / l_[0];
    float inv1 = 1.0f / l_[1];
    int s0 = qb * 128 + w16 + g;
    int s1 = s0 + 8;
#pragma unroll
    for (int ni = 0; ni < 8; ni++) {
        int d2 = ni * 8 + 2 * t4;
        *(float2*)&g_O[((size_t)b_ * SEQ + s0) * DIMM + h * HDIM + d2] =
            make_float2(tfr(o[ni][0] * inv0), tfr(o[ni][1] * inv0));
        *(float2*)&g_O[((size_t)b_ * SEQ + s1) * DIMM + h * HDIM + d2] =
            make_float2(tfr(o[ni][2] * inv1), tfr(o[ni][3] * inv1));
    }
}

// ---------------------------------------------------------------------------
// Launch
// ---------------------------------------------------------------------------
extern "C" void kernel_launch(void* const* d_in, const int* in_sizes, int n_in,
                              void* d_out, int out_size)
{
    const float* x      = (const float*)d_in[0];
    const float* W_qkv  = (const float*)d_in[1];
    const float* b_qkv  = (const float*)d_in[2];
    const float* W_proj = (const float*)d_in[3];
    const float* b_proj = (const float*)d_in[4];
    float* out = (float*)d_out;

    const int gemm_smem  = (2 * AS_WORDS + 2 * BS_WORDS) * (int)sizeof(unsigned);          // 71680
    const int flash_smem = (2 * KS_WORDS + 2 * VS_WORDS + 128 * PS_STR) * (int)sizeof(unsigned); // 106496

    // Pre-pass: tf32-round x / W_qkv / W_proj into device-global copies
    {
        int n4x = (MTOK * DIMM) / 4;        // 2097152
        int n4q = (DIMM * NQKV) / 4;        // 786432
        int n4p = (DIMM * DIMM) / 4;        // 262144
        round_prepass<0><<<(n4x + 255) / 256, 256>>>(x, n4x);
        round_prepass<1><<<(n4q + 255) / 256, 256>>>(W_qkv, n4q);
        round_prepass<2><<<(n4p + 255) / 256, 256>>>(W_proj, n4p);
    }

    // GEMM1: QKV projection + scatter
    {
        cudaFuncSetAttribute(gemm_mma_kernel<true>,
                             cudaFuncAttributeMaxDynamicSharedMemorySize, gemm_smem);
        dim3 grid(NQKV / 128, MTOK / 128);   // (24, 64)
        gemm_mma_kernel<true><<<grid, 256, gemm_smem>>>(b_qkv, nullptr);
    }

    // Flash attention
    {
        cudaFuncSetAttribute(flash_mma_kernel,
                             cudaFuncAttributeMaxDynamicSharedMemorySize, flash_smem);
        dim3 grid(BATCH * NHEAD, SEQ / 128); // (64, 16)
        flash_mma_kernel<<<grid, 256, flash_smem>>>();
    }

    // GEMM2: output projection
    {
        cudaFuncSetAttribute(gemm_mma_kernel<false>,
                             cudaFuncAttributeMaxDynamicSharedMemorySize, gemm_smem);
        dim3 grid(DIMM / 128, MTOK / 128);   // (8, 64)
        gemm_mma_kernel<false><<<grid, 256, gemm_smem>>>(b_proj, out);
    }
}